// round 10
// baseline (speedup 1.0000x reference)
#include <cuda_runtime.h>
#include <cstdint>

// FlowNet-C correlation cost via warp-level fp16 mma.sync, single-term,
// h-paired CTAs.
// out[b,h,w, tj*21+ti] = (1/256) * sum_c A[b,h,w,c] * B[b, h+2tj-20, w+2ti-20, c]
// A,B: [16,48,64,256] f32. Out: [16,48,64,441] f32.
//
// CTA = (h-pair (h0,h0+2), b, w-parity). Row h0 at dy=t and row h0+2 at
// dy=t-1 read the SAME B row r = h0-20+2t -> one plane stream feeds both.
// 8 warps = hsel(2) x M2 x N2, each m16 n16 FULL-K -> final accumulators,
// register-direct epilogue. One __syncthreads per interval. dy loop runs
// only the valid B-row range; invalid (h,dy) outputs zero-filled in prologue.

#define BATCH 16
#define HH 48
#define WW 64
#define CC 256

#define RS 264                      // fp16 row stride (528B, conflict-free ldmatrix)
#define RSB (RS * 2)
#define PLANE 16896                 // 32 rows * 528B
#define ROWSET_B (2 * PLANE)        // per (b,h): parity0 hi, parity1 hi

#define SM_TOTAL (4 * PLANE)        // 67584 -> 3 CTAs/SM

// B pre-converted to fp16 hi planes
__device__ unsigned char g_B[(size_t)BATCH * HH * ROWSET_B];

// ---------------- helpers ----------------
__device__ __forceinline__ uint32_t smem_u32(const void* p) {
    uint32_t a;
    asm("{ .reg .u64 t; cvta.to.shared.u64 t, %1; cvt.u32.u64 %0, t; }"
        : "=r"(a) : "l"(p));
    return a;
}
__device__ __forceinline__ uint32_t cvt_f16x2(float x0, float x1) {
    uint32_t h;
    asm("cvt.rn.f16x2.f32 %0, %1, %2;" : "=r"(h) : "f"(x1), "f"(x0));
    return h;
}
__device__ __forceinline__ void ldmx4(uint32_t* r, uint32_t addr) {
    asm volatile("ldmatrix.sync.aligned.m8n8.x4.shared.b16 {%0,%1,%2,%3}, [%4];"
        : "=r"(r[0]), "=r"(r[1]), "=r"(r[2]), "=r"(r[3]) : "r"(addr));
}
__device__ __forceinline__ void mma_f16(float* c, const uint32_t* a, const uint32_t* b) {
    asm volatile("mma.sync.aligned.m16n8k16.row.col.f32.f16.f16.f32 "
        "{%0,%1,%2,%3}, {%4,%5,%6,%7}, {%8,%9}, {%0,%1,%2,%3};"
        : "+f"(c[0]), "+f"(c[1]), "+f"(c[2]), "+f"(c[3])
        : "r"(a[0]), "r"(a[1]), "r"(a[2]), "r"(a[3]), "r"(b[0]), "r"(b[1]));
}
__device__ __forceinline__ void cpa16(uint32_t dst, const void* src) {
    asm volatile("cp.async.cg.shared.global [%0], [%1], 16;"
                 :: "r"(dst), "l"(src) : "memory");
}
// fill one 16896B plane: 1056 chunks = 4*256 + 32
__device__ __forceinline__ void fill_plane(uint32_t dst, const unsigned char* srow, int tid) {
    #pragma unroll
    for (int j = 0; j < 4; ++j)
        cpa16(dst + (uint32_t)(tid + j * 256) * 16, srow + (size_t)(tid + j * 256) * 16);
    if (tid < 32)
        cpa16(dst + (uint32_t)(tid + 1024) * 16, srow + (size_t)(tid + 1024) * 16);
}

// ---------------- pre-pass: B fp32 -> fp16 hi planes ----------------
__global__ void convert_b_kernel(const float* __restrict__ B) {
    const int bh = blockIdx.x;                 // b*48 + h
    const float4* src = (const float4*)(B + (size_t)bh * WW * CC);
    unsigned char* dst = g_B + (size_t)bh * ROWSET_B;
    #pragma unroll
    for (int j = 0; j < 16; ++j) {
        const int id = threadIdx.x + j * 256;  // float4 id over 64x256
        const int u = id >> 6, c4 = id & 63;
        float4 v = src[id];
        uint32_t h0 = cvt_f16x2(v.x, v.y);
        uint32_t h1 = cvt_f16x2(v.z, v.w);
        const uint32_t off = (u & 1) * PLANE + (u >> 1) * RSB + c4 * 8;
        *(uint2*)(dst + off) = make_uint2(h0, h1);
    }
}

// ---------------- main kernel ----------------
__global__ __launch_bounds__(256, 3)
void corr_mma_kernel(const float* __restrict__ A, float* __restrict__ O)
{
    extern __shared__ unsigned char smem[];
    const uint32_t sb = smem_u32(smem);
    const int tid  = threadIdx.x;
    const int lane = tid & 31;
    const int wid  = tid >> 5;
    const int hsel = wid & 1;          // which h row of the pair
    const int nh   = (wid >> 1) & 1;   // N half (16 u')
    const int mh   = (wid >> 2) & 1;   // M half (16 w')
    const int h0   = 4 * blockIdx.x + (blockIdx.z >> 1);   // pair = (h0, h0+2)
    const int bb   = blockIdx.y;
    const int p    = blockIdx.z & 1;   // w parity

    // valid B-row index range: r(t) = h0 - 20 + 2t in [0, HH)
    const int TL = max(0, (21 - h0) >> 1);
    const int TH = min(21, (67 - h0) >> 1);

    const unsigned char* const browset = g_B + (size_t)(bb * HH) * ROWSET_B + p * PLANE;

    // --- prologue prefetch: planes for t = TL, TL+1 ---
    fill_plane(sb + (uint32_t)(TL & 3) * PLANE,
               browset + (size_t)(h0 - 20 + 2 * TL) * ROWSET_B, tid);
    asm volatile("cp.async.commit_group;" ::: "memory");
    if (TL + 1 <= TH)
        fill_plane(sb + (uint32_t)((TL + 1) & 3) * PLANE,
                   browset + (size_t)(h0 - 18 + 2 * TL) * ROWSET_B, tid);
    asm volatile("cp.async.commit_group;" ::: "memory");

    // --- zero-fill invalid (h,dy) output rows (overlaps cp.async) ---
    #pragma unroll
    for (int rsel = 0; rsel < 2; ++rsel) {
        const int lo = rsel ? max(TL - 1, 0) : TL;
        const int hi = rsel ? min(TH - 1, 20) : min(TH, 20);
        float* ob = O + ((size_t)(bb * HH + h0 + 2 * rsel) * WW + p) * 441;
        for (int dy = 0; dy < 21; ++dy) {
            if (dy >= lo && dy <= hi) continue;
            for (int o = tid; o < 672; o += 256) {
                const int w2 = o / 21, ti = o - w2 * 21;
                ob[(size_t)w2 * 882 + dy * 21 + ti] = 0.0f;
            }
        }
    }

    // --- stage A rows h0, h0+2 (parity-p w) into planes (TL+2)&3, (TL+3)&3 ---
    #pragma unroll
    for (int rsel = 0; rsel < 2; ++rsel) {
        const int w2 = tid >> 3, seg = tid & 7;    // 32 channels per seg
        const float4* asrc = (const float4*)(A
            + ((size_t)(bb * HH + h0 + 2 * rsel) * WW + 2 * w2 + p) * CC) + seg * 8;
        const uint32_t dsth = sb + (uint32_t)((TL + 2 + rsel) & 3) * PLANE
                              + (uint32_t)w2 * RSB + seg * 64;
        #pragma unroll
        for (int j = 0; j < 8; ++j) {
            float4 v = asrc[j];
            uint32_t c0 = cvt_f16x2(v.x, v.y);
            uint32_t c1 = cvt_f16x2(v.z, v.w);
            asm volatile("st.shared.v2.b32 [%0], {%1,%2};"
                         :: "r"(dsth + j * 8), "r"(c0), "r"(c1) : "memory");
        }
    }
    __syncthreads();

    // --- A-hi fragments (m16 x k256 of this warp's h row) -> registers ---
    uint32_t ahi[16][4];
    {
        const uint32_t ab = sb + (uint32_t)((TL + 2 + hsel) & 3) * PLANE
                            + (uint32_t)(mh * 16 + (lane & 15)) * RSB + (lane >> 4) * 16;
        #pragma unroll
        for (int kt = 0; kt < 16; ++kt)
            ldmx4(ahi[kt], ab + kt * 32);
    }
    __syncthreads();   // A staging planes free for B ring after this

    // B fragment offset within a plane (x4: n16 x k16)
    const uint32_t boff = (uint32_t)(nh * 16 + ((lane >> 4) << 3) + (lane & 7)) * RSB
                          + ((lane >> 3) & 1) * 16;
    const float inv = 1.0f / 256.0f;

    for (int t = TL; t <= TH; ++t) {
        // prefetch plane t+2 (ring distance 2; reuse fenced by prior barrier)
        if (t + 2 <= TH)
            fill_plane(sb + (uint32_t)((t + 2) & 3) * PLANE,
                       browset + (size_t)(h0 - 16 + 2 * t) * ROWSET_B, tid);
        asm volatile("cp.async.commit_group;" ::: "memory");
        asm volatile("cp.async.wait_group 2;" ::: "memory");
        __syncthreads();                 // plane t ready; old plane LDSMs done

        const int dy = t - hsel;         // this warp's displacement index
        if ((unsigned)dy <= 20u) {
            float acc0[4] = {0.f, 0.f, 0.f, 0.f};
            float acc1[4] = {0.f, 0.f, 0.f, 0.f};
            const uint32_t bbase = sb + (uint32_t)(t & 3) * PLANE + boff;
            #pragma unroll
            for (int kt = 0; kt < 16; ++kt) {
                uint32_t b4[4];
                ldmx4(b4, bbase + kt * 32);
                mma_f16(acc0, ahi[kt], b4);
                mma_f16(acc1, ahi[kt], b4 + 2);
            }

            // epilogue: registers -> gmem, band extract + phantom zero fill
            const int R  = lane >> 2;
            const int C0 = nh * 16 + (lane & 3) * 2;
            float* const obase = O + ((size_t)(bb * HH + h0 + 2 * hsel) * WW + p) * 441
                                 + (size_t)dy * 21;
            #pragma unroll
            for (int rr = 0; rr < 2; ++rr) {
                const int w2 = mh * 16 + R + rr * 8;
                float* orow = obase + (size_t)w2 * 882;   // w = 2*w2+p
                #pragma unroll
                for (int cg = 0; cg < 2; ++cg) {
                    const int ti = C0 + cg * 8 - w2 + 10;
                    const float v0 = (cg ? acc1 : acc0)[rr * 2 + 0] * inv;
                    const float v1 = (cg ? acc1 : acc0)[rr * 2 + 1] * inv;
                    if ((unsigned)ti < 21u)       orow[ti]     = v0;
                    if ((unsigned)(ti + 1) < 21u) orow[ti + 1] = v1;
                }
                // phantom zeros (u outside [0,W)): nh0 -> left band, nh1 -> right
                if ((lane & 3) == 0) {
                    if (nh == 0) {
                        const int nz = 10 - w2;
                        for (int j = 0; j < nz; ++j) orow[j] = 0.0f;
                    } else {
                        const int nz = w2 - 21;
                        for (int j = 0; j < nz; ++j) orow[20 - j] = 0.0f;
                    }
                }
            }
        }
    }
}

extern "C" void kernel_launch(void* const* d_in, const int* in_sizes, int n_in,
                              void* d_out, int out_size)
{
    const float* A = (const float*)d_in[0];
    const float* B = (const float*)d_in[1];
    float* O = (float*)d_out;

    static int configured = 0;
    if (!configured) {
        cudaFuncSetAttribute(corr_mma_kernel,
                             cudaFuncAttributeMaxDynamicSharedMemorySize,
                             SM_TOTAL);
        configured = 1;
    }

    convert_b_kernel<<<BATCH * HH, 256>>>(B);
    dim3 grid(12, BATCH, 4);
    corr_mma_kernel<<<grid, 256, SM_TOTAL>>>(A, O);
}

// round 11
// speedup vs baseline: 1.1055x; 1.1055x over previous
#include <cuda_runtime.h>
#include <cstdint>

// FlowNet-C correlation cost via warp-level fp16 mma.sync, single-term.
// out[b,h,w, tj*21+ti] = (1/256) * sum_c A[b,h,w,c] * B[b, h+2tj-20, w+2ti-20, c]
// A,B: [16,48,64,256] f32. Out: [16,48,64,441] f32.
//
// CTA = (h, b, parity). Per dy: GEMM D[32 w-half, 32 u-half, K=256] in fp16.
// 8 warps = M2 x N2 x DY2, each m16 n16 full-K -> final accumulators.
// R11: FOUR independent accumulator chains per warp (even/odd kt split,
// folded at epilogue) to break the HMMA dependency-latency wall; phantom
// band zeros hoisted into the convert pre-pass.

#define BATCH 16
#define HH 48
#define WW 64
#define CC 256
#define NDY 21

#define RS 264                      // fp16 row stride (528B, conflict-free ldmatrix)
#define RSB (RS * 2)
#define PLANE 16896                 // 32 rows * 528B
#define ROWSET_B (2 * PLANE)        // per (b,h): parity0 hi, parity1 hi

#define SM_TOTAL (4 * PLANE)        // 67584 -> 3 CTAs/SM

// B pre-converted to fp16 hi planes
__device__ unsigned char g_B[(size_t)BATCH * HH * ROWSET_B];

// ---------------- helpers ----------------
__device__ __forceinline__ uint32_t smem_u32(const void* p) {
    uint32_t a;
    asm("{ .reg .u64 t; cvta.to.shared.u64 t, %1; cvt.u32.u64 %0, t; }"
        : "=r"(a) : "l"(p));
    return a;
}
__device__ __forceinline__ uint32_t cvt_f16x2(float x0, float x1) {
    uint32_t h;
    asm("cvt.rn.f16x2.f32 %0, %1, %2;" : "=r"(h) : "f"(x1), "f"(x0));
    return h;
}
__device__ __forceinline__ void ldmx4(uint32_t* r, uint32_t addr) {
    asm volatile("ldmatrix.sync.aligned.m8n8.x4.shared.b16 {%0,%1,%2,%3}, [%4];"
        : "=r"(r[0]), "=r"(r[1]), "=r"(r[2]), "=r"(r[3]) : "r"(addr));
}
__device__ __forceinline__ void mma_f16(float* c, const uint32_t* a, const uint32_t* b) {
    asm volatile("mma.sync.aligned.m16n8k16.row.col.f32.f16.f16.f32 "
        "{%0,%1,%2,%3}, {%4,%5,%6,%7}, {%8,%9}, {%0,%1,%2,%3};"
        : "+f"(c[0]), "+f"(c[1]), "+f"(c[2]), "+f"(c[3])
        : "r"(a[0]), "r"(a[1]), "r"(a[2]), "r"(a[3]), "r"(b[0]), "r"(b[1]));
}
__device__ __forceinline__ void cpa16(uint32_t dst, const void* src) {
    asm volatile("cp.async.cg.shared.global [%0], [%1], 16;"
                 :: "r"(dst), "l"(src) : "memory");
}
// fill one 16896B plane: 1056 chunks = 4*256 + 32
__device__ __forceinline__ void fill_plane(uint32_t dst, const unsigned char* srow, int tid) {
    #pragma unroll
    for (int j = 0; j < 4; ++j)
        cpa16(dst + (uint32_t)(tid + j * 256) * 16, srow + (size_t)(tid + j * 256) * 16);
    if (tid < 32)
        cpa16(dst + (uint32_t)(tid + 1024) * 16, srow + (size_t)(tid + 1024) * 16);
}

// ---------------- pre-pass: B fp32 -> fp16 hi planes + phantom zero fill ----
__global__ void convert_b_kernel(const float* __restrict__ B, float* __restrict__ O) {
    const int bh = blockIdx.x;                 // b*48 + h
    const float4* src = (const float4*)(B + (size_t)bh * WW * CC);
    unsigned char* dst = g_B + (size_t)bh * ROWSET_B;
    #pragma unroll
    for (int j = 0; j < 16; ++j) {
        const int id = threadIdx.x + j * 256;  // float4 id over 64x256
        const int u = id >> 6, c4 = id & 63;
        float4 v = src[id];
        uint32_t h0 = cvt_f16x2(v.x, v.y);
        uint32_t h1 = cvt_f16x2(v.z, v.w);
        const uint32_t off = (u & 1) * PLANE + (u >> 1) * RSB + c4 * 8;
        *(uint2*)(dst + off) = make_uint2(h0, h1);
    }
    // phantom ti positions (u = w + 2ti - 20 outside [0,W)): zero for all dy
    float* ob = O + (size_t)bh * WW * 441;
    for (int idx = threadIdx.x; idx < WW * 21; idx += 256) {
        const int w = idx / 21, ti = idx - (idx / 21) * 21;
        const int u = w + 2 * ti - 20;
        if ((unsigned)u >= (unsigned)WW) {
            float* row = ob + (size_t)w * 441 + ti;
            #pragma unroll
            for (int dy = 0; dy < 21; ++dy) row[dy * 21] = 0.0f;
        }
    }
}

// ---------------- main kernel ----------------
__global__ __launch_bounds__(256, 3)
void corr_mma_kernel(const float* __restrict__ A, float* __restrict__ O)
{
    extern __shared__ unsigned char smem[];
    const uint32_t sb = smem_u32(smem);
    const int tid  = threadIdx.x;
    const int lane = tid & 31;
    const int wid  = tid >> 5;
    const int dyh = wid & 1;           // dy slot within the pair
    const int nh  = (wid >> 1) & 1;    // N half (16 u')
    const int mh  = (wid >> 2) & 1;    // M half (16 w')
    const int h   = blockIdx.x;
    const int bb  = blockIdx.y;
    const int p   = blockIdx.z;        // parity

    const unsigned char* const browset = g_B + (size_t)(bb * HH) * ROWSET_B + p * PLANE;

    // --- prologue prefetch: B(dy0)->plane0, B(dy1)->plane1 ---
    #pragma unroll
    for (int f = 0; f < 2; ++f) {
        const int hb = h + 2 * f - 20;
        if ((unsigned)hb < (unsigned)HH)
            fill_plane(sb + (uint32_t)f * PLANE, browset + (size_t)hb * ROWSET_B, tid);
        asm volatile("cp.async.commit_group;" ::: "memory");
    }

    // --- stage A row (this parity's 32 w) -> fp16 hi into plane 2 ---
    {
        const int w2 = tid >> 3, seg = tid & 7;    // 32 channels per seg
        const float4* asrc = (const float4*)(A
            + ((size_t)(bb * HH + h) * WW + 2 * w2 + p) * CC) + seg * 8;
        const uint32_t dsth = sb + 2 * PLANE + (uint32_t)w2 * RSB + seg * 64;
        #pragma unroll
        for (int j = 0; j < 8; ++j) {
            float4 v = asrc[j];
            uint32_t c0 = cvt_f16x2(v.x, v.y);
            uint32_t c1 = cvt_f16x2(v.z, v.w);
            asm volatile("st.shared.v2.b32 [%0], {%1,%2};"
                         :: "r"(dsth + j * 8), "r"(c0), "r"(c1) : "memory");
        }
    }
    __syncthreads();

    // --- A-hi fragments (m16 x k256) -> registers for the whole dy loop ---
    uint32_t ahi[16][4];
    {
        const uint32_t ab = sb + 2 * PLANE + (uint32_t)(mh * 16 + (lane & 15)) * RSB
                            + (lane >> 4) * 16;
        #pragma unroll
        for (int kt = 0; kt < 16; ++kt)
            ldmx4(ahi[kt], ab + kt * 32);
    }
    __syncthreads();   // planes 2,3 free for B ring after this

    // B fragment offset within a plane (x4: n16 x k16)
    const uint32_t boff = (uint32_t)(nh * 16 + ((lane >> 4) << 3) + (lane & 7)) * RSB
                          + ((lane >> 3) & 1) * 16;
    const float inv = 1.0f / 256.0f;

    for (int dyi = 0; dyi < NDY; dyi += 2) {
        // prefetch dy = dyi+2, dyi+3 into ring planes
        #pragma unroll
        for (int f = 2; f < 4; ++f) {
            const int dyf = dyi + f;
            const int hb = h + 2 * dyf - 20;
            if (dyf < NDY && (unsigned)hb < (unsigned)HH)
                fill_plane(sb + (uint32_t)(dyf & 3) * PLANE,
                           browset + (size_t)hb * ROWSET_B, tid);
            asm volatile("cp.async.commit_group;" ::: "memory");
        }
        asm volatile("cp.async.wait_group 2;" ::: "memory");
        __syncthreads();                 // planes dyi, dyi+1 ready

        const int dy = dyi + dyh;
        const int hb = h + 2 * dy - 20;

        // four independent accumulator chains (even/odd kt)
        float a0a[4] = {0.f,0.f,0.f,0.f}, a0b[4] = {0.f,0.f,0.f,0.f};
        float a1a[4] = {0.f,0.f,0.f,0.f}, a1b[4] = {0.f,0.f,0.f,0.f};
        if (dy < NDY && (unsigned)hb < (unsigned)HH) {
            const uint32_t bbase = sb + (uint32_t)(dy & 3) * PLANE + boff;
            #pragma unroll
            for (int kp = 0; kp < 8; ++kp) {
                uint32_t b4[4];
                ldmx4(b4, bbase + (2 * kp) * 32);
                mma_f16(a0a, ahi[2 * kp], b4);
                mma_f16(a1a, ahi[2 * kp], b4 + 2);
                ldmx4(b4, bbase + (2 * kp + 1) * 32);
                mma_f16(a0b, ahi[2 * kp + 1], b4);
                mma_f16(a1b, ahi[2 * kp + 1], b4 + 2);
            }
        }
        __syncthreads();                 // all LDSM done before next refill

        // epilogue: fold chains, registers -> gmem band extract
        if (dy < NDY) {
            float acc0[4], acc1[4];
            #pragma unroll
            for (int i = 0; i < 4; ++i) {
                acc0[i] = (a0a[i] + a0b[i]) * inv;
                acc1[i] = (a1a[i] + a1b[i]) * inv;
            }
            const int R  = lane >> 2;
            const int C0 = nh * 16 + (lane & 3) * 2;
            float* const obase = O + ((size_t)(bb * HH + h) * WW + p) * 441
                                 + (size_t)dy * 21;
            #pragma unroll
            for (int rr = 0; rr < 2; ++rr) {
                const int w2 = mh * 16 + R + rr * 8;
                float* orow = obase + (size_t)w2 * 882;   // w = 2*w2+p
                #pragma unroll
                for (int cg = 0; cg < 2; ++cg) {
                    const int ti = C0 + cg * 8 - w2 + 10;
                    const float v0 = (cg ? acc1 : acc0)[rr * 2 + 0];
                    const float v1 = (cg ? acc1 : acc0)[rr * 2 + 1];
                    if ((unsigned)ti < 21u)       orow[ti]     = v0;
                    if ((unsigned)(ti + 1) < 21u) orow[ti + 1] = v1;
                }
            }
        }
    }
}

extern "C" void kernel_launch(void* const* d_in, const int* in_sizes, int n_in,
                              void* d_out, int out_size)
{
    const float* A = (const float*)d_in[0];
    const float* B = (const float*)d_in[1];
    float* O = (float*)d_out;

    static int configured = 0;
    if (!configured) {
        cudaFuncSetAttribute(corr_mma_kernel,
                             cudaFuncAttributeMaxDynamicSharedMemorySize,
                             SM_TOTAL);
        configured = 1;
    }

    convert_b_kernel<<<BATCH * HH, 256>>>(B, O);
    dim3 grid(HH, BATCH, 2);
    corr_mma_kernel<<<grid, 256, SM_TOTAL>>>(A, O);
}